// round 1
// baseline (speedup 1.0000x reference)
#include <cuda_runtime.h>
#include <stdint.h>

// ChamferLoss2D: N=16 batches, P=4096 points per set, D=2.
// cost_n = 0.5*(mean_i min_j C_ij + mean_j min_i C_ij), C = sqrt(clip(|x-y|^2, EPS))
// out = mean_n cost_n * (sum(set2_n) >= 0)
//
// Strategy: min/sqrt/clip commute (all monotone), so compute min of squared
// distance per point, sqrt once per point. Inner loop uses x^2+y^2-2xy with
// y^2 precomputed in smem and x^2 folded out of the loop (exact: addition is
// monotone). Packed f32x2 mul/fma does 2 y-points per instruction.

#define N_BATCH 16
#define P 4096
#define TPB 256
#define XPT 8                   // x points per thread
#define XCHUNK (TPB * XPT)      // 2048 x points per block
#define NXCHUNKS (P / XCHUNK)   // 2
#define YSPLITS 8
#define YTILE (P / YSPLITS)     // 512 y points per block

#define EPS 1e-12f

// Scratch: per-direction, per-batch, per-point min squared distance,
// stored as uint bits (values are >= EPS > 0, so uint order == float order).
__device__ unsigned int g_min[2][N_BATCH][P];

__global__ void __launch_bounds__(TPB) init_kernel(float* out) {
    int idx = blockIdx.x * TPB + threadIdx.x;
    ((unsigned int*)g_min)[idx] = 0x7f7fffffu;  // FLT_MAX bits
    if (idx == 0) out[0] = 0.0f;
}

__global__ void __launch_bounds__(TPB) chamfer_min_kernel(
    const float* __restrict__ s1, const float* __restrict__ s2) {
    const int ysplit = blockIdx.x;
    const int xc     = blockIdx.y % NXCHUNKS;
    const int n      = blockIdx.y / NXCHUNKS;
    const int dir    = blockIdx.z;

    const float* X = (dir == 0) ? s1 : s2;
    const float* Y = (dir == 0) ? s2 : s1;
    X += (size_t)n * P * 2;
    Y += (size_t)n * P * 2;

    __shared__ __align__(16) float ys0[YTILE];
    __shared__ __align__(16) float ys1[YTILE];
    __shared__ __align__(16) float ysq[YTILE];

    const int t = threadIdx.x;

    // Cooperatively load the y tile; precompute y0, y1, y0^2+y1^2.
#pragma unroll
    for (int k = 0; k < YTILE / TPB; k++) {
        int j = t + k * TPB;
        float2 y = ((const float2*)Y)[ysplit * YTILE + j];
        ys0[j] = y.x;
        ys1[j] = y.y;
        ysq[j] = y.x * y.x + y.y * y.y;
    }

    // Load this thread's 8 x points (strided for coalescing), splat into f32x2.
    unsigned long long px0[XPT], px1[XPT];
    float x2[XPT], mlo[XPT], mhi[XPT];
#pragma unroll
    for (int k = 0; k < XPT; k++) {
        int xi = xc * XCHUNK + t + k * TPB;
        float2 x = ((const float2*)X)[xi];
        asm("mov.b64 %0, {%1, %1};" : "=l"(px0[k]) : "f"(x.x));
        asm("mov.b64 %0, {%1, %1};" : "=l"(px1[k]) : "f"(x.y));
        x2[k]  = x.x * x.x + x.y * x.y;
        mlo[k] = 3.0e38f;
        mhi[k] = 3.0e38f;
    }
    unsigned long long NEG2;
    asm("mov.b64 %0, {%1, %1};" : "=l"(NEG2) : "f"(-2.0f));

    __syncthreads();

    // Inner loop: 2 y points per iteration via packed f32x2.
    // d_partial = ysq - 2*(x0*y0 + x1*y1)   (x^2 added after the min: exact)
#pragma unroll 2
    for (int j = 0; j < YTILE; j += 2) {
        unsigned long long y0p = *(const unsigned long long*)(ys0 + j);
        unsigned long long y1p = *(const unsigned long long*)(ys1 + j);
        unsigned long long yqp = *(const unsigned long long*)(ysq + j);
#pragma unroll
        for (int k = 0; k < XPT; k++) {
            float dlo, dhi;
            asm("{\n\t"
                ".reg .b64 t1, d;\n\t"
                "mul.rn.f32x2 t1, %2, %3;\n\t"
                "fma.rn.f32x2 t1, %4, %5, t1;\n\t"
                "fma.rn.f32x2 d, t1, %6, %7;\n\t"
                "mov.b64 {%0, %1}, d;\n\t"
                "}"
                : "=f"(dlo), "=f"(dhi)
                : "l"(px0[k]), "l"(y0p), "l"(px1[k]), "l"(y1p),
                  "l"(NEG2), "l"(yqp));
            mlo[k] = fminf(mlo[k], dlo);
            mhi[k] = fminf(mhi[k], dhi);
        }
    }

    // Merge lo/hi halves, add x^2, clamp at EPS, merge across y-split blocks.
#pragma unroll
    for (int k = 0; k < XPT; k++) {
        float v = fminf(mlo[k], mhi[k]) + x2[k];
        v = fmaxf(v, EPS);
        int xi = xc * XCHUNK + t + k * TPB;
        atomicMin(&g_min[dir][n][xi], __float_as_uint(v));
    }
}

__global__ void __launch_bounds__(TPB) finalize_kernel(
    const float* __restrict__ s2, float* __restrict__ out) {
    const int n = blockIdx.x;
    const int t = threadIdx.x;

    float sum1 = 0.0f, sum2 = 0.0f, msum = 0.0f;
    for (int i = t; i < P; i += TPB) {
        sum1 += sqrtf(__uint_as_float(g_min[0][n][i]));
        sum2 += sqrtf(__uint_as_float(g_min[1][n][i]));
    }
    const float* p2 = s2 + (size_t)n * 2 * P;
    for (int i = t; i < 2 * P; i += TPB) msum += p2[i];

#pragma unroll
    for (int o = 16; o > 0; o >>= 1) {
        sum1 += __shfl_down_sync(0xffffffffu, sum1, o);
        sum2 += __shfl_down_sync(0xffffffffu, sum2, o);
        msum += __shfl_down_sync(0xffffffffu, msum, o);
    }
    __shared__ float r1[TPB / 32], r2[TPB / 32], rm[TPB / 32];
    if ((t & 31) == 0) {
        r1[t >> 5] = sum1;
        r2[t >> 5] = sum2;
        rm[t >> 5] = msum;
    }
    __syncthreads();
    if (t == 0) {
        float a = 0.0f, b = 0.0f, c = 0.0f;
#pragma unroll
        for (int w = 0; w < TPB / 32; w++) { a += r1[w]; b += r2[w]; c += rm[w]; }
        if (c >= 0.0f) {
            float cost = 0.5f * (a + b) * (1.0f / (float)P);
            atomicAdd(out, cost * (1.0f / (float)N_BATCH));
        }
    }
}

extern "C" void kernel_launch(void* const* d_in, const int* in_sizes, int n_in,
                              void* d_out, int out_size) {
    const float* s1 = (const float*)d_in[0];  // point_set_1: [16,4096,2] f32
    const float* s2 = (const float*)d_in[1];  // point_set_2: [16,4096,2] f32
    float* out = (float*)d_out;

    init_kernel<<<(2 * N_BATCH * P) / TPB, TPB>>>(out);

    dim3 grid(YSPLITS, N_BATCH * NXCHUNKS, 2);  // 8 x 32 x 2 = 512 blocks
    chamfer_min_kernel<<<grid, TPB>>>(s1, s2);

    finalize_kernel<<<N_BATCH, TPB>>>(s2, out);
}

// round 2
// speedup vs baseline: 1.3292x; 1.3292x over previous
#include <cuda_runtime.h>
#include <stdint.h>

// ChamferLoss2D: N=16, P=4096, D=2.
// cost_n = 0.5*(mean_i min_j C_ij + mean_j min_i C_ij), C = sqrt(clip(|x-y|^2, EPS))
// out = mean_n cost_n * (sum(set2_n) >= 0)
//
// min/sqrt/clip commute (monotone) -> min of squared distance, sqrt per point.
// Inner loop: d_partial = fma(-2x0, y0, fma(-2x1, y1, ysq))  [2 packed f32x2
// fmas per 2 y-points], x^2 folded out of the min (exact). Partial mins per
// y-split written as plain stores; finalize min-reduces + sqrt + masked mean.

#define N_BATCH 16
#define P 4096
#define TPB 256
#define XPT 8                   // x points per thread
#define XCHUNK (TPB * XPT)      // 2048
#define NXCHUNKS (P / XCHUNK)   // 2
#define YSPLITS 16
#define YTILE (P / YSPLITS)     // 256

#define EPS 1e-12f

__device__ float g_part[2][N_BATCH][YSPLITS][P];   // per-split min sq-dist (clamped)
__device__ float g_mask[N_BATCH];

// ---- prep: zero the output, compute per-batch masks -------------------------
__global__ void __launch_bounds__(TPB) prep_kernel(
    const float* __restrict__ s2, float* __restrict__ out) {
    const int n = blockIdx.x;
    const int t = threadIdx.x;
    float s = 0.0f;
    const float* p = s2 + (size_t)n * 2 * P;
    for (int i = t; i < 2 * P; i += TPB) s += p[i];
#pragma unroll
    for (int o = 16; o > 0; o >>= 1) s += __shfl_down_sync(0xffffffffu, s, o);
    __shared__ float r[TPB / 32];
    if ((t & 31) == 0) r[t >> 5] = s;
    __syncthreads();
    if (t == 0) {
        float a = 0.0f;
#pragma unroll
        for (int w = 0; w < TPB / 32; w++) a += r[w];
        g_mask[n] = (a >= 0.0f) ? 1.0f : 0.0f;
        if (n == 0) out[0] = 0.0f;
    }
}

// ---- main: per-(dir, n, xchunk, ysplit) partial min -------------------------
__global__ void __launch_bounds__(TPB) chamfer_min_kernel(
    const float* __restrict__ s1, const float* __restrict__ s2) {
    const int ysplit = blockIdx.x;
    const int xc     = blockIdx.y % NXCHUNKS;
    const int n      = blockIdx.y / NXCHUNKS;
    const int dir    = blockIdx.z;

    const float* X = (dir == 0) ? s1 : s2;
    const float* Y = (dir == 0) ? s2 : s1;
    X += (size_t)n * P * 2;
    Y += (size_t)n * P * 2;

    __shared__ __align__(16) float ys0[YTILE];
    __shared__ __align__(16) float ys1[YTILE];
    __shared__ __align__(16) float ysq[YTILE];

    const int t = threadIdx.x;

    // Load y tile (one point per thread): y0, y1, y0^2+y1^2.
    {
        float2 y = ((const float2*)Y)[ysplit * YTILE + t];
        ys0[t] = y.x;
        ys1[t] = y.y;
        ysq[t] = y.x * y.x + y.y * y.y;
    }

    // This thread's 8 x points: splat -2*x0, -2*x1 into f32x2 pairs.
    unsigned long long a0[XPT], a1[XPT];
    float x2[XPT], mlo[XPT], mhi[XPT];
#pragma unroll
    for (int k = 0; k < XPT; k++) {
        int xi = xc * XCHUNK + t + k * TPB;
        float2 x = ((const float2*)X)[xi];
        float m0 = -2.0f * x.x;
        float m1 = -2.0f * x.y;
        asm("mov.b64 %0, {%1, %1};" : "=l"(a0[k]) : "f"(m0));
        asm("mov.b64 %0, {%1, %1};" : "=l"(a1[k]) : "f"(m1));
        x2[k]  = x.x * x.x + x.y * x.y;
        mlo[k] = 3.0e38f;
        mhi[k] = 3.0e38f;
    }

    __syncthreads();

    // 2 y points / iter: d_partial = (-2x0)*y0 + (-2x1)*y1 + ysq  (2 packed fmas)
#pragma unroll 2
    for (int j = 0; j < YTILE; j += 2) {
        unsigned long long y0p = *(const unsigned long long*)(ys0 + j);
        unsigned long long y1p = *(const unsigned long long*)(ys1 + j);
        unsigned long long yqp = *(const unsigned long long*)(ysq + j);
#pragma unroll
        for (int k = 0; k < XPT; k++) {
            float dlo, dhi;
            asm("{\n\t"
                ".reg .b64 d;\n\t"
                "fma.rn.f32x2 d, %4, %5, %6;\n\t"
                "fma.rn.f32x2 d, %2, %3, d;\n\t"
                "mov.b64 {%0, %1}, d;\n\t"
                "}"
                : "=f"(dlo), "=f"(dhi)
                : "l"(a0[k]), "l"(y0p), "l"(a1[k]), "l"(y1p), "l"(yqp));
            mlo[k] = fminf(mlo[k], dlo);
            mhi[k] = fminf(mhi[k], dhi);
        }
    }

    // Merge halves, add x^2, clamp, store partial (plain STG, coalesced).
    float* dst = &g_part[dir][n][ysplit][xc * XCHUNK];
#pragma unroll
    for (int k = 0; k < XPT; k++) {
        float v = fminf(mlo[k], mhi[k]) + x2[k];
        dst[t + k * TPB] = fmaxf(v, EPS);
    }
}

// ---- finalize: min over ysplits, sqrt, masked mean --------------------------
__global__ void __launch_bounds__(TPB) finalize_kernel(float* __restrict__ out) {
    // 512 blocks: blockIdx.x -> (dir, n, xbase)
    const int xblk = blockIdx.x % (P / TPB);
    const int n    = (blockIdx.x / (P / TPB)) % N_BATCH;
    const int dir  = blockIdx.x / (P / TPB * N_BATCH);
    const int t    = threadIdx.x;
    const int x    = xblk * TPB + t;

    float m = g_part[dir][n][0][x];
#pragma unroll
    for (int s = 1; s < YSPLITS; s++) m = fminf(m, g_part[dir][n][s][x]);
    float v = sqrtf(m);

#pragma unroll
    for (int o = 16; o > 0; o >>= 1) v += __shfl_down_sync(0xffffffffu, v, o);
    __shared__ float r[TPB / 32];
    if ((t & 31) == 0) r[t >> 5] = v;
    __syncthreads();
    if (t == 0) {
        float a = 0.0f;
#pragma unroll
        for (int w = 0; w < TPB / 32; w++) a += r[w];
        // weight: 0.5 (two directions) * 1/P (mean over points) * 1/N (mean over batch)
        atomicAdd(out, a * g_mask[n] * (0.5f / (float)P / (float)N_BATCH));
    }
}

extern "C" void kernel_launch(void* const* d_in, const int* in_sizes, int n_in,
                              void* d_out, int out_size) {
    const float* s1 = (const float*)d_in[0];  // point_set_1: [16,4096,2] f32
    const float* s2 = (const float*)d_in[1];  // point_set_2: [16,4096,2] f32
    float* out = (float*)d_out;

    prep_kernel<<<N_BATCH, TPB>>>(s2, out);

    dim3 grid(YSPLITS, N_BATCH * NXCHUNKS, 2);  // 16 x 32 x 2 = 1024 blocks
    chamfer_min_kernel<<<grid, TPB>>>(s1, s2);

    finalize_kernel<<<2 * N_BATCH * (P / TPB), TPB>>>(out);
}

// round 3
// speedup vs baseline: 1.3298x; 1.0005x over previous
#include <cuda_runtime.h>
#include <stdint.h>

// ChamferLoss2D: N=16, P=4096, D=2.
// cost_n = 0.5*(mean_i min_j C + mean_j min_i C), C = sqrt(clip(|x-y|^2, EPS))
// out = mean_n cost_n * (sum(set2_n) >= 0)
//
// min/sqrt/clip commute -> min of squared distance, sqrt once per point.
// Per pair: d_partial = fma(-2x0,y0, fma(-2x1,y1, ysq)) with packed f32x2
// (2 y-points per fma chain), x^2 folded out of the min (exact).
// Launch order: main FIRST (ncu -s 5 -c 1 lands on kernel #0 of a call).

#define N_BATCH 16
#define P 4096
#define TPB 256
#define XPT 8                   // x points per thread
#define XCHUNK (TPB * XPT)      // 2048
#define NXCHUNKS (P / XCHUNK)   // 2
#define YSPLITS 32
#define YTILE (P / YSPLITS)     // 128

#define EPS 1e-12f

__device__ float g_part[2][N_BATCH][YSPLITS][P];   // per-split min sq-dist (clamped)
__device__ float g_mask[N_BATCH];

// ---- main: per-(dir, n, xchunk, ysplit) partial min -------------------------
__global__ void __launch_bounds__(TPB) chamfer_min_kernel(
    const float* __restrict__ s1, const float* __restrict__ s2) {
    const int ysplit = blockIdx.x;
    const int xc     = blockIdx.y % NXCHUNKS;
    const int n      = blockIdx.y / NXCHUNKS;
    const int dir    = blockIdx.z;

    const float* X = (dir == 0) ? s1 : s2;
    const float* Y = (dir == 0) ? s2 : s1;
    X += (size_t)n * P * 2;
    Y += (size_t)n * P * 2;

    // Packed y tile: yp[jj] = {y0[2jj], y0[2jj+1], y1[2jj], y1[2jj+1]},
    //                yq[jj] = {ysq[2jj], ysq[2jj+1]}
    __shared__ __align__(16) float4 yp[YTILE / 2];
    __shared__ __align__(16) float2 yq[YTILE / 2];

    const int t = threadIdx.x;

    if (t < YTILE) {
        float2 y = ((const float2*)Y)[ysplit * YTILE + t];
        float* ypf = (float*)yp;
        ypf[(t >> 1) * 4 + (t & 1)]     = y.x;
        ypf[(t >> 1) * 4 + 2 + (t & 1)] = y.y;
        ((float*)yq)[t] = y.x * y.x + y.y * y.y;
    }

    // This thread's 8 x points: splat -2*x0, -2*x1 into f32x2 pairs.
    unsigned long long a0[XPT], a1[XPT];
    float x2[XPT], mlo[XPT], mhi[XPT];
#pragma unroll
    for (int k = 0; k < XPT; k++) {
        int xi = xc * XCHUNK + t + k * TPB;
        float2 x = ((const float2*)X)[xi];
        float m0 = -2.0f * x.x;
        float m1 = -2.0f * x.y;
        asm("mov.b64 %0, {%1, %1};" : "=l"(a0[k]) : "f"(m0));
        asm("mov.b64 %0, {%1, %1};" : "=l"(a1[k]) : "f"(m1));
        x2[k]  = x.x * x.x + x.y * x.y;
        mlo[k] = 3.0e38f;
        mhi[k] = 3.0e38f;
    }

    __syncthreads();

    // 2 y points / iter: 2 packed fmas + 2 mins per x point.
#pragma unroll 2
    for (int jj = 0; jj < YTILE / 2; jj++) {
        float4 ypv = yp[jj];
        float2 yqv = yq[jj];
        unsigned long long y0p, y1p, yqp;
        asm("mov.b64 %0, {%1, %2};" : "=l"(y0p) : "f"(ypv.x), "f"(ypv.y));
        asm("mov.b64 %0, {%1, %2};" : "=l"(y1p) : "f"(ypv.z), "f"(ypv.w));
        asm("mov.b64 %0, {%1, %2};" : "=l"(yqp) : "f"(yqv.x), "f"(yqv.y));
#pragma unroll
        for (int k = 0; k < XPT; k++) {
            asm("{\n\t"
                ".reg .b64 d;\n\t"
                ".reg .f32 lo, hi;\n\t"
                "fma.rn.f32x2 d, %2, %3, %4;\n\t"
                "fma.rn.f32x2 d, %5, %6, d;\n\t"
                "mov.b64 {lo, hi}, d;\n\t"
                "min.f32 %0, %0, lo;\n\t"
                "min.f32 %1, %1, hi;\n\t"
                "}"
                : "+f"(mlo[k]), "+f"(mhi[k])
                : "l"(a1[k]), "l"(y1p), "l"(yqp), "l"(a0[k]), "l"(y0p));
        }
    }

    // Merge halves, add x^2, clamp, store partial (coalesced plain STG).
    float* dst = &g_part[dir][n][ysplit][xc * XCHUNK];
#pragma unroll
    for (int k = 0; k < XPT; k++) {
        float v = fminf(mlo[k], mhi[k]) + x2[k];
        dst[t + k * TPB] = fmaxf(v, EPS);
    }
}

// ---- maskprep: per-batch mask, zero the output ------------------------------
__global__ void __launch_bounds__(TPB) maskprep_kernel(
    const float* __restrict__ s2, float* __restrict__ out) {
    const int n = blockIdx.x;
    const int t = threadIdx.x;
    const float4* p = (const float4*)(s2 + (size_t)n * 2 * P);
    float s = 0.0f;
#pragma unroll
    for (int i = 0; i < (2 * P / 4) / TPB; i++) {   // 8 float4 per thread
        float4 v = p[t + i * TPB];
        s += (v.x + v.y) + (v.z + v.w);
    }
#pragma unroll
    for (int o = 16; o > 0; o >>= 1) s += __shfl_down_sync(0xffffffffu, s, o);
    __shared__ float r[TPB / 32];
    if ((t & 31) == 0) r[t >> 5] = s;
    __syncthreads();
    if (t == 0) {
        float a = 0.0f;
#pragma unroll
        for (int w = 0; w < TPB / 32; w++) a += r[w];
        g_mask[n] = (a >= 0.0f) ? 1.0f : 0.0f;
        if (n == 0) out[0] = 0.0f;
    }
}

// ---- reduce: min over ysplits, sqrt, masked mean -> atomicAdd(out) ----------
__global__ void __launch_bounds__(TPB) reduce_kernel(float* __restrict__ out) {
    const int xblk = blockIdx.x % (P / TPB);
    const int n    = (blockIdx.x / (P / TPB)) % N_BATCH;
    const int dir  = blockIdx.x / (P / TPB * N_BATCH);
    const int t    = threadIdx.x;
    const int x    = xblk * TPB + t;

    float m = g_part[dir][n][0][x];
#pragma unroll
    for (int s = 1; s < YSPLITS; s++) m = fminf(m, g_part[dir][n][s][x]);
    float v = sqrtf(m);

#pragma unroll
    for (int o = 16; o > 0; o >>= 1) v += __shfl_down_sync(0xffffffffu, v, o);
    __shared__ float r[TPB / 32];
    if ((t & 31) == 0) r[t >> 5] = v;
    __syncthreads();
    if (t == 0) {
        float a = 0.0f;
#pragma unroll
        for (int w = 0; w < TPB / 32; w++) a += r[w];
        // weight: 0.5 (two dirs) * 1/P (mean over points) * 1/N (mean over batch)
        atomicAdd(out, a * g_mask[n] * (0.5f / (float)P / (float)N_BATCH));
    }
}

extern "C" void kernel_launch(void* const* d_in, const int* in_sizes, int n_in,
                              void* d_out, int out_size) {
    const float* s1 = (const float*)d_in[0];  // point_set_1: [16,4096,2] f32
    const float* s2 = (const float*)d_in[1];  // point_set_2: [16,4096,2] f32
    float* out = (float*)d_out;

    dim3 grid(YSPLITS, N_BATCH * NXCHUNKS, 2);  // 32 x 32 x 2 = 2048 blocks
    chamfer_min_kernel<<<grid, TPB>>>(s1, s2);  // kernel #0 -> gets profiled

    maskprep_kernel<<<N_BATCH, TPB>>>(s2, out);

    reduce_kernel<<<2 * N_BATCH * (P / TPB), TPB>>>(out);
}

// round 4
// speedup vs baseline: 1.4543x; 1.0936x over previous
#include <cuda_runtime.h>
#include <stdint.h>
#include <float.h>

// ChamferLoss2D: N=16, P=4096, D=2.
// cost_n = 0.5*(mean_i min_j C + mean_j min_i C), C = sqrt(clip(|x-y|^2, EPS))
// out = mean_n cost_n * (sum(set2_n) >= 0)
//
// O(P) grid-based exact nearest neighbor instead of O(P^2) brute force:
//  build_kernel: per (set,batch), count-sort points into a GxG uniform grid.
//  query_kernel: per query point, expanding-ring search with exact
//  lower-bound early termination (conservative at edges; full-coverage
//  fallback => exact min for ANY input data).

#define N_BATCH 16
#define P 4096
#define TPB 256

#define G 96
#define CELLS (G * G)            // 9216
#define CPT (CELLS / TPB)        // 36 cells per thread in scan
#define PPT (P / TPB)            // 16 points per thread in build

#define DOM_LO (-5.2f)
#define DOM_W  (10.4f)
#define CELL_W (DOM_W / (float)G)
#define INV_W  ((float)G / DOM_W)

#define EPS 1e-12f
#define OUT_WT (0.5f / (float)P / (float)N_BATCH)

__device__ float2   g_pts[2][N_BATCH][P];            // cell-sorted points
__device__ uint32_t g_cellstart[2][N_BATCH][CELLS + 1];
__device__ float    g_mask[N_BATCH];

__device__ __forceinline__ int cell_coord(float v) {
    int c = (int)((v - DOM_LO) * INV_W);
    return min(max(c, 0), G - 1);
}

// ---- build: one block per (set, batch): histogram -> scan -> scatter --------
__global__ void __launch_bounds__(TPB) build_kernel(
    const float* __restrict__ s1, const float* __restrict__ s2,
    float* __restrict__ out) {
    const int set = blockIdx.x >> 4;
    const int n   = blockIdx.x & 15;
    const float2* __restrict__ src =
        (const float2*)((set ? s2 : s1) + (size_t)n * P * 2);

    __shared__ uint32_t s_cnt[CELLS];
    __shared__ uint32_t s_wsum[TPB / 32];
    __shared__ float    s_red[TPB / 32];

    const int t = threadIdx.x;
    const int lane = t & 31, w = t >> 5;

#pragma unroll
    for (int k = 0; k < CPT; k++) s_cnt[k * TPB + t] = 0;
    __syncthreads();

    float2 pt[PPT];
    int    cid[PPT];
    float  msum = 0.0f;
#pragma unroll
    for (int k = 0; k < PPT; k++) {
        float2 p = src[k * TPB + t];
        pt[k] = p;
        cid[k] = cell_coord(p.y) * G + cell_coord(p.x);
        atomicAdd(&s_cnt[cid[k]], 1u);
        msum += p.x + p.y;
    }
    __syncthreads();

    // Exclusive scan over CELLS: thread owns cells [t*CPT, t*CPT+CPT).
    uint32_t tot = 0;
#pragma unroll
    for (int c = 0; c < CPT; c++) tot += s_cnt[t * CPT + c];
    uint32_t inc = tot;
#pragma unroll
    for (int o = 1; o < 32; o <<= 1) {
        uint32_t v = __shfl_up_sync(0xffffffffu, inc, o);
        if (lane >= o) inc += v;
    }
    if (lane == 31) s_wsum[w] = inc;
    uint32_t excl = inc - tot;
    __syncthreads();
    uint32_t wbase = 0;
#pragma unroll
    for (int ww = 0; ww < TPB / 32; ww++) {
        uint32_t v = s_wsum[ww];
        if (ww < w) wbase += v;
    }
    uint32_t run = wbase + excl;
#pragma unroll
    for (int c = 0; c < CPT; c++) {
        uint32_t v = s_cnt[t * CPT + c];
        s_cnt[t * CPT + c] = run;
        run += v;
    }
    __syncthreads();

    // Publish cell starts to global.
    uint32_t* __restrict__ gs = g_cellstart[set][n];
#pragma unroll
    for (int k = 0; k < CPT; k++) gs[k * TPB + t] = s_cnt[k * TPB + t];
    if (t == 0) gs[CELLS] = P;
    __syncthreads();  // global writes read s_cnt before scatter mutates it

    // Scatter points into sorted order.
    float2* __restrict__ gp = g_pts[set][n];
#pragma unroll
    for (int k = 0; k < PPT; k++) {
        uint32_t pos = atomicAdd(&s_cnt[cid[k]], 1u);
        gp[pos] = pt[k];
    }

    // Mask (set 2 only) + zero the output once.
#pragma unroll
    for (int o = 16; o > 0; o >>= 1) msum += __shfl_down_sync(0xffffffffu, msum, o);
    if (lane == 0) s_red[w] = msum;
    __syncthreads();
    if (t == 0) {
        float a = 0.0f;
#pragma unroll
        for (int ww = 0; ww < TPB / 32; ww++) a += s_red[ww];
        if (set == 1) g_mask[n] = (a >= 0.0f) ? 1.0f : 0.0f;
        if (set == 0 && n == 0) out[0] = 0.0f;
    }
}

// ---- query: expanding-ring exact NN, block-reduce, masked atomicAdd ---------
__device__ __forceinline__ void scan_run(
    const float2* __restrict__ pts, uint32_t s, uint32_t e,
    float qx, float qy, float& best) {
    for (uint32_t idx = s; idx < e; idx++) {
        float2 p = pts[idx];
        float dx = qx - p.x;
        float dy = qy - p.y;
        best = fminf(best, fmaf(dx, dx, dy * dy));
    }
}

__global__ void __launch_bounds__(TPB) query_kernel(float* __restrict__ out) {
    // blockIdx: [dir(2)][n(16)][chunk(16)]
    const int chunk = blockIdx.x & 15;
    const int n     = (blockIdx.x >> 4) & 15;
    const int dir   = blockIdx.x >> 8;
    const int src   = dir;        // dir0: queries from set1(idx0) vs set2(idx1)
    const int dst   = 1 - dir;
    const int t     = threadIdx.x;

    const float2 q = g_pts[src][n][chunk * TPB + t];
    const float2* __restrict__ pts = g_pts[dst][n];
    const uint32_t* __restrict__ cs = g_cellstart[dst][n];

    const int cx = cell_coord(q.x);
    const int cy = cell_coord(q.y);

    float best = FLT_MAX;

    // Box radius 1 (rings 0 and 1): three contiguous row-runs.
    {
        int ilo = max(cx - 1, 0), ihi = min(cx + 1, G - 1);
        int jlo = max(cy - 1, 0), jhi = min(cy + 1, G - 1);
        for (int j = jlo; j <= jhi; j++)
            scan_run(pts, cs[j * G + ilo], cs[j * G + ihi + 1], q.x, q.y, best);
    }

    int r = 1;
    while (true) {
        // Full coverage -> exact, stop.
        if (cx - r <= 0 && cx + r >= G - 1 && cy - r <= 0 && cy + r >= G - 1)
            break;
        // Lower bound: distance from q to the boundary of the scanned box.
        float xlo = DOM_LO + (float)(cx - r) * CELL_W;
        float xhi = DOM_LO + (float)(cx + r + 1) * CELL_W;
        float ylo = DOM_LO + (float)(cy - r) * CELL_W;
        float yhi = DOM_LO + (float)(cy + r + 1) * CELL_W;
        float lb = fminf(fminf(q.x - xlo, xhi - q.x), fminf(q.y - ylo, yhi - q.y));
        if (lb > 0.0f && best <= lb * lb) break;

        r++;
        // Scan ring r: two full rows + two side columns.
        int ilo = max(cx - r, 0), ihi = min(cx + r, G - 1);
        int jt = cy - r, jb = cy + r;
        if (jt >= 0)
            scan_run(pts, cs[jt * G + ilo], cs[jt * G + ihi + 1], q.x, q.y, best);
        if (jb <= G - 1)
            scan_run(pts, cs[jb * G + ilo], cs[jb * G + ihi + 1], q.x, q.y, best);
        int jlo2 = max(cy - r + 1, 0), jhi2 = min(cy + r - 1, G - 1);
        for (int j = jlo2; j <= jhi2; j++) {
            if (cx - r >= 0) {
                int c = j * G + (cx - r);
                scan_run(pts, cs[c], cs[c + 1], q.x, q.y, best);
            }
            if (cx + r <= G - 1) {
                int c = j * G + (cx + r);
                scan_run(pts, cs[c], cs[c + 1], q.x, q.y, best);
            }
        }
    }

    float d = sqrtf(fmaxf(best, EPS));

    // Block reduce (all threads share (dir, n)).
#pragma unroll
    for (int o = 16; o > 0; o >>= 1) d += __shfl_down_sync(0xffffffffu, d, o);
    __shared__ float s_red[TPB / 32];
    if ((t & 31) == 0) s_red[t >> 5] = d;
    __syncthreads();
    if (t == 0) {
        float a = 0.0f;
#pragma unroll
        for (int ww = 0; ww < TPB / 32; ww++) a += s_red[ww];
        atomicAdd(out, a * g_mask[n] * OUT_WT);
    }
}

extern "C" void kernel_launch(void* const* d_in, const int* in_sizes, int n_in,
                              void* d_out, int out_size) {
    const float* s1 = (const float*)d_in[0];  // point_set_1: [16,4096,2] f32
    const float* s2 = (const float*)d_in[1];  // point_set_2: [16,4096,2] f32
    float* out = (float*)d_out;

    build_kernel<<<2 * N_BATCH, TPB>>>(s1, s2, out);
    query_kernel<<<2 * N_BATCH * (P / TPB), TPB>>>(out);
}